// round 16
// baseline (speedup 1.0000x reference)
#include <cuda_runtime.h>

// IF neuron multi-step scan, hard reset:
//   h_t = x_t + v_{t-1};  s_t = (h_t >= 1) ? 1 : 0;  v_t = s_t ? 0 : h_t
//
// FINAL (confirmed twice at 45.568us wall — R10 and R15 identical):
//   block=128, one float4 lane per thread, batch-4 double-buffered prefetch
//   (8 LDG.128 in flight per thread), plain __ldcs/__stcs,
//   __launch_bounds__(128,10) -> regs=48, 10 blocks/SM, 1.38 waves.
//
// Floor analysis (validated over 15 rounds): 268MB compulsory L2 traffic
// (134MB read + 134MB write, zero reuse, fp32 output) at the
// path-independent LTS cap (~6300B/cyc) ≈ 37-38us kernel. All variants —
// MLP 2-8, occ 40-77%, 128/256-bit, cp.async pipelines, L2 evict policies —
// converged here. createpolicy variants looked ~1us faster under ncu
// (cold-cache, --cache-control all) but were consistently ~1.8us slower on
// steady-state graph-replay wall time; wall is ground truth.
// The T-recurrence (hard reset) is not affine-composable, so T cannot be
// parallelized to fix wave quantization; bytes are irreducible.

__device__ __forceinline__ float4 if_step(float4 xv, float4& v)
{
    float h0 = xv.x + v.x;
    float h1 = xv.y + v.y;
    float h2 = xv.z + v.z;
    float h3 = xv.w + v.w;

    float4 s;
    s.x = (h0 >= 1.0f) ? 1.0f : 0.0f;
    s.y = (h1 >= 1.0f) ? 1.0f : 0.0f;
    s.z = (h2 >= 1.0f) ? 1.0f : 0.0f;
    s.w = (h3 >= 1.0f) ? 1.0f : 0.0f;

    v.x = (h0 >= 1.0f) ? 0.0f : h0;
    v.y = (h1 >= 1.0f) ? 0.0f : h1;
    v.z = (h2 >= 1.0f) ? 0.0f : h2;
    v.w = (h3 >= 1.0f) ? 0.0f : h3;
    return s;
}

#define BLOCK 128

// T must be a multiple of 4 (T=32 here).
__global__ __launch_bounds__(BLOCK, 10) void if_scan_b4_128(
    const float4* __restrict__ x,   // [T, n4]
    const float4* __restrict__ v0,  // [n4]
    float4* __restrict__ out,       // [T, n4]
    int n4, int T)
{
    int i = blockIdx.x * BLOCK + threadIdx.x;
    if (i >= n4) return;

    float4 v = v0[i];
    const float4* xp = x + i;
    float4* op = out + i;

    long long stride = n4;

    // prologue: load batch 0
    float4 buf[4];
    #pragma unroll
    for (int k = 0; k < 4; ++k)
        buf[k] = __ldcs(xp + (long long)k * stride);
    xp += 4 * stride;

    for (int t = 4; t < T; t += 4) {
        // prefetch next batch (8 loads in flight per thread)
        float4 nxt[4];
        #pragma unroll
        for (int k = 0; k < 4; ++k)
            nxt[k] = __ldcs(xp + (long long)k * stride);
        xp += 4 * stride;

        // compute + store current batch (write burst)
        #pragma unroll
        for (int k = 0; k < 4; ++k) {
            float4 s = if_step(buf[k], v);
            __stcs(op, s);
            op += stride;
        }

        #pragma unroll
        for (int k = 0; k < 4; ++k) buf[k] = nxt[k];
    }

    // epilogue
    #pragma unroll
    for (int k = 0; k < 4; ++k) {
        float4 s = if_step(buf[k], v);
        __stcs(op, s);
        op += stride;
    }
}

// Generic fallback for T not divisible by 4 (not hit for this shape).
__global__ __launch_bounds__(BLOCK) void if_scan_plain(
    const float4* __restrict__ x,
    const float4* __restrict__ v0,
    float4* __restrict__ out,
    int n4, int T)
{
    int i = blockIdx.x * BLOCK + threadIdx.x;
    if (i >= n4) return;

    float4 v = v0[i];
    const float4* xp = x + i;
    float4* op = out + i;

    for (int t = 0; t < T; ++t) {
        float4 xv = __ldcs(xp); xp += n4;
        float4 s = if_step(xv, v);
        __stcs(op, s); op += n4;
    }
}

extern "C" void kernel_launch(void* const* d_in, const int* in_sizes, int n_in,
                              void* d_out, int out_size)
{
    const float* x_seq  = (const float*)d_in[0];   // [T, B, D]
    const float* v_init = (const float*)d_in[1];   // [B, D]

    int N = in_sizes[1];              // B * D
    int T = in_sizes[0] / N;          // timesteps
    int n4 = N / 4;

    int grid = (n4 + BLOCK - 1) / BLOCK;

    if ((T & 3) == 0) {
        if_scan_b4_128<<<grid, BLOCK>>>(
            (const float4*)x_seq, (const float4*)v_init,
            (float4*)d_out, n4, T);
    } else {
        if_scan_plain<<<grid, BLOCK>>>(
            (const float4*)x_seq, (const float4*)v_init,
            (float4*)d_out, n4, T);
    }
}

// round 17
// speedup vs baseline: 1.0105x; 1.0105x over previous
#include <cuda_runtime.h>

// IF neuron multi-step scan, hard reset:
//   h_t = x_t + v_{t-1};  s_t = (h_t >= 1) ? 1 : 0;  v_t = s_t ? 0 : h_t
//
// FINAL (locked; walls 45.568 / 45.568 / 46.016 over three runs):
//   block=128, one float4 lane per thread, batch-4 double-buffered prefetch
//   (8 LDG.128 in flight per thread), plain __ldcs/__stcs,
//   __launch_bounds__(128,10) -> regs=48, 10 blocks/SM, 1.38 waves.
//
// Closed search space (all axes measured both directions):
//   - bytes: 268MB compulsory L2 traffic at the LTS cap ≈ 37-38us kernel;
//     zero reuse, fp32 output, full-sector stores, writes traverse LTS even
//     when L2-absorbed (policy experiments R8/R11-R14).
//   - regs-vs-waves: 14 blocks/SM needs <=36 regs, but MLP=8 needs ~48;
//     every lower-MLP variant measured worse (R1/R4/R6).
//   - thread count: halving threads for wider/more per-thread work measured
//     worse twice (R2/R9).
//   - cache policies: ~1us better under ncu cold-cache, ~1.8us worse on
//     ground-truth steady-state wall (n=4). Wall is the metric.
//   - T cannot be parallelized (hard reset is not affine-composable) without
//     adding traffic.

__device__ __forceinline__ float4 if_step(float4 xv, float4& v)
{
    float h0 = xv.x + v.x;
    float h1 = xv.y + v.y;
    float h2 = xv.z + v.z;
    float h3 = xv.w + v.w;

    float4 s;
    s.x = (h0 >= 1.0f) ? 1.0f : 0.0f;
    s.y = (h1 >= 1.0f) ? 1.0f : 0.0f;
    s.z = (h2 >= 1.0f) ? 1.0f : 0.0f;
    s.w = (h3 >= 1.0f) ? 1.0f : 0.0f;

    v.x = (h0 >= 1.0f) ? 0.0f : h0;
    v.y = (h1 >= 1.0f) ? 0.0f : h1;
    v.z = (h2 >= 1.0f) ? 0.0f : h2;
    v.w = (h3 >= 1.0f) ? 0.0f : h3;
    return s;
}

#define BLOCK 128

// T must be a multiple of 4 (T=32 here).
__global__ __launch_bounds__(BLOCK, 10) void if_scan_b4_128(
    const float4* __restrict__ x,   // [T, n4]
    const float4* __restrict__ v0,  // [n4]
    float4* __restrict__ out,       // [T, n4]
    int n4, int T)
{
    int i = blockIdx.x * BLOCK + threadIdx.x;
    if (i >= n4) return;

    float4 v = v0[i];
    const float4* xp = x + i;
    float4* op = out + i;

    long long stride = n4;

    // prologue: load batch 0
    float4 buf[4];
    #pragma unroll
    for (int k = 0; k < 4; ++k)
        buf[k] = __ldcs(xp + (long long)k * stride);
    xp += 4 * stride;

    for (int t = 4; t < T; t += 4) {
        // prefetch next batch (8 loads in flight per thread)
        float4 nxt[4];
        #pragma unroll
        for (int k = 0; k < 4; ++k)
            nxt[k] = __ldcs(xp + (long long)k * stride);
        xp += 4 * stride;

        // compute + store current batch (write burst)
        #pragma unroll
        for (int k = 0; k < 4; ++k) {
            float4 s = if_step(buf[k], v);
            __stcs(op, s);
            op += stride;
        }

        #pragma unroll
        for (int k = 0; k < 4; ++k) buf[k] = nxt[k];
    }

    // epilogue
    #pragma unroll
    for (int k = 0; k < 4; ++k) {
        float4 s = if_step(buf[k], v);
        __stcs(op, s);
        op += stride;
    }
}

// Generic fallback for T not divisible by 4 (not hit for this shape).
__global__ __launch_bounds__(BLOCK) void if_scan_plain(
    const float4* __restrict__ x,
    const float4* __restrict__ v0,
    float4* __restrict__ out,
    int n4, int T)
{
    int i = blockIdx.x * BLOCK + threadIdx.x;
    if (i >= n4) return;

    float4 v = v0[i];
    const float4* xp = x + i;
    float4* op = out + i;

    for (int t = 0; t < T; ++t) {
        float4 xv = __ldcs(xp); xp += n4;
        float4 s = if_step(xv, v);
        __stcs(op, s); op += n4;
    }
}

extern "C" void kernel_launch(void* const* d_in, const int* in_sizes, int n_in,
                              void* d_out, int out_size)
{
    const float* x_seq  = (const float*)d_in[0];   // [T, B, D]
    const float* v_init = (const float*)d_in[1];   // [B, D]

    int N = in_sizes[1];              // B * D
    int T = in_sizes[0] / N;          // timesteps
    int n4 = N / 4;

    int grid = (n4 + BLOCK - 1) / BLOCK;

    if ((T & 3) == 0) {
        if_scan_b4_128<<<grid, BLOCK>>>(
            (const float4*)x_seq, (const float4*)v_init,
            (float4*)d_out, n4, T);
    } else {
        if_scan_plain<<<grid, BLOCK>>>(
            (const float4*)x_seq, (const float4*)v_init,
            (float4*)d_out, n4, T);
    }
}